// round 3
// baseline (speedup 1.0000x reference)
#include <cuda_runtime.h>
#include <cstdint>

#define SEQ 4096
#define EMB 1024
#define NH  16
#define HD  64
#define KPAD 72   // SMEM row pitch (floats) for K/V/P tiles: 72%32=8 -> conflict-free frag loads

// Scratch: __device__ globals (no runtime allocation).
// g_Q/g_K/g_V hold tf32-rounded bit patterns (stored as float) so flash does no cvt.
__device__ float g_Q[NH * SEQ * HD];   // [h][s][d], pre-scaled by 1/sqrt(64), tf32 bits
__device__ float g_K[NH * SEQ * HD];   // [h][s][d], tf32 bits
__device__ float g_V[NH * SEQ * HD];   // [h][s][d], tf32 bits
__device__ float g_O[SEQ * EMB];       // [s][e] attention output (fp32)

__device__ __forceinline__ uint32_t f2tf(float f) {
    uint32_t u; asm("cvt.rna.tf32.f32 %0, %1;" : "=r"(u) : "f"(f)); return u;
}

// D = A(16x8,row) * B(8x8,col) + D, tf32 in, f32 accum
__device__ __forceinline__ void mma8(float* c, const uint32_t* a, const uint32_t* b) {
    asm volatile(
        "mma.sync.aligned.m16n8k8.row.col.f32.tf32.tf32.f32 "
        "{%0,%1,%2,%3}, {%4,%5,%6,%7}, {%8,%9}, {%0,%1,%2,%3};"
        : "+f"(c[0]), "+f"(c[1]), "+f"(c[2]), "+f"(c[3])
        : "r"(a[0]), "r"(a[1]), "r"(a[2]), "r"(a[3]), "r"(b[0]), "r"(b[1]));
}

__device__ __forceinline__ void cp16(void* dst, const void* src) {
    uint32_t d = (uint32_t)__cvta_generic_to_shared(dst);
    asm volatile("cp.async.cg.shared.global [%0], [%1], 16;" :: "r"(d), "l"(src));
}
__device__ __forceinline__ void cp_commit() { asm volatile("cp.async.commit_group;"); }
__device__ __forceinline__ void cp_wait0()  { asm volatile("cp.async.wait_group 0;" ::: "memory"); }

// ---------------------------------------------------------------------------
// 128x128x32-tile TF32 GEMM body:  C = (A[4096xE] @ W[ExE] + bias) * scale
// 256 threads = 8 warps (4 row-strips of 32 x 2 col-strips of 64).
// A pitch 36, B pitch 136 -> conflict-free fragment loads.
// ---------------------------------------------------------------------------
__device__ __forceinline__ void gemm128(
    const float* __restrict__ A, const float* __restrict__ W,
    const float* __restrict__ bias, float* __restrict__ C,
    float scale, int head_split, int tf32_out,
    uint32_t* As, uint32_t* Bs)
{
    const int tid = threadIdx.x, lane = tid & 31, w = tid >> 5;
    const int g = lane >> 2, tig = lane & 3;
    const int wr = w >> 1, wc = w & 1;
    const int m0 = blockIdx.y * 128, n0 = blockIdx.x * 128;

    float acc[2][8][4];
#pragma unroll
    for (int s = 0; s < 2; s++)
#pragma unroll
        for (int n = 0; n < 8; n++)
#pragma unroll
            for (int i = 0; i < 4; i++) acc[s][n][i] = 0.f;

    float4 ar[4], br[4];
#pragma unroll
    for (int j = 0; j < 4; j++) {
        int idx = tid + j * 256;
        ar[j] = *(const float4*)&A[(m0 + (idx >> 3)) * EMB + ((idx & 7) << 2)];
        br[j] = *(const float4*)&W[(idx >> 5) * EMB + n0 + ((idx & 31) << 2)];
    }

    for (int kt = 0; kt < 32; kt++) {
        __syncthreads();
#pragma unroll
        for (int j = 0; j < 4; j++) {
            int idx = tid + j * 256;
            uint32_t* pa = &As[(idx >> 3) * 36 + ((idx & 7) << 2)];
            pa[0] = f2tf(ar[j].x); pa[1] = f2tf(ar[j].y);
            pa[2] = f2tf(ar[j].z); pa[3] = f2tf(ar[j].w);
            uint32_t* pb = &Bs[(idx >> 5) * 136 + ((idx & 31) << 2)];
            pb[0] = f2tf(br[j].x); pb[1] = f2tf(br[j].y);
            pb[2] = f2tf(br[j].z); pb[3] = f2tf(br[j].w);
        }
        __syncthreads();
        if (kt < 31) {
#pragma unroll
            for (int j = 0; j < 4; j++) {
                int idx = tid + j * 256;
                ar[j] = *(const float4*)&A[(m0 + (idx >> 3)) * EMB + (kt + 1) * 32 + ((idx & 7) << 2)];
                br[j] = *(const float4*)&W[((kt + 1) * 32 + (idx >> 5)) * EMB + n0 + ((idx & 31) << 2)];
            }
        }
#pragma unroll
        for (int kk = 0; kk < 4; kk++) {
            uint32_t af[2][4];
#pragma unroll
            for (int s = 0; s < 2; s++) {
                int rb = wr * 32 + s * 16;
                af[s][0] = As[(rb + g)     * 36 + kk * 8 + tig];
                af[s][1] = As[(rb + g + 8) * 36 + kk * 8 + tig];
                af[s][2] = As[(rb + g)     * 36 + kk * 8 + tig + 4];
                af[s][3] = As[(rb + g + 8) * 36 + kk * 8 + tig + 4];
            }
#pragma unroll
            for (int n = 0; n < 8; n++) {
                uint32_t bb[2];
                bb[0] = Bs[(kk * 8 + tig)     * 136 + wc * 64 + n * 8 + g];
                bb[1] = Bs[(kk * 8 + tig + 4) * 136 + wc * 64 + n * 8 + g];
                mma8(acc[0][n], af[0], bb);
                mma8(acc[1][n], af[1], bb);
            }
        }
    }

    // epilogue: bias + scale (+ optional tf32 rounding) direct from registers
#pragma unroll
    for (int s = 0; s < 2; s++) {
        int r0 = m0 + wr * 32 + s * 16 + g, r1 = r0 + 8;
#pragma unroll
        for (int n = 0; n < 8; n++) {
            int cc = n0 + wc * 64 + n * 8 + 2 * tig;
            float b0 = bias[cc], b1 = bias[cc + 1];
            float v00 = (acc[s][n][0] + b0) * scale, v01 = (acc[s][n][1] + b1) * scale;
            float v10 = (acc[s][n][2] + b0) * scale, v11 = (acc[s][n][3] + b1) * scale;
            if (tf32_out) {
                v00 = __uint_as_float(f2tf(v00)); v01 = __uint_as_float(f2tf(v01));
                v10 = __uint_as_float(f2tf(v10)); v11 = __uint_as_float(f2tf(v11));
            }
            if (head_split) {
                int hh = cc >> 6, d = cc & 63;
                *(float2*)&C[(hh * SEQ + r0) * HD + d] = make_float2(v00, v01);
                *(float2*)&C[(hh * SEQ + r1) * HD + d] = make_float2(v10, v11);
            } else {
                *(float2*)&C[r0 * EMB + cc] = make_float2(v00, v01);
                *(float2*)&C[r1 * EMB + cc] = make_float2(v10, v11);
            }
        }
    }
}

__global__ __launch_bounds__(256) void qkv_gemm(
    const float* __restrict__ x,
    const float* __restrict__ Wq, const float* __restrict__ Wk, const float* __restrict__ Wv,
    const float* __restrict__ bq, const float* __restrict__ bk, const float* __restrict__ bv)
{
    __shared__ uint32_t As[128 * 36];
    __shared__ uint32_t Bs[32 * 136];
    const float* W = Wq; const float* bi = bq; float* C = g_Q; float sc = 0.125f;
    if (blockIdx.z == 1) { W = Wk; bi = bk; C = g_K; sc = 1.0f; }
    if (blockIdx.z == 2) { W = Wv; bi = bv; C = g_V; sc = 1.0f; }
    gemm128(x, W, bi, C, sc, /*head_split=*/1, /*tf32_out=*/1, As, Bs);
}

__global__ __launch_bounds__(256) void out_gemm(
    const float* __restrict__ Wo, const float* __restrict__ bo, float* __restrict__ out)
{
    __shared__ uint32_t As[128 * 36];
    __shared__ uint32_t Bs[32 * 136];
    gemm128(g_O, Wo, bo, out, 1.0f, /*head_split=*/0, /*tf32_out=*/0, As, Bs);
}

// ---------------------------------------------------------------------------
// Flash attention: 1 CTA per (128 q-rows, head). 8 warps x 16 q-rows each.
// S and O live in registers; softmax via quad shuffles; P round-trips through
// a per-warp SMEM strip; K/V tiles cp.async double-buffered (tf32 pre-converted).
// Dynamic SMEM: Ks[2]+Vs[2] (4*64*72 u32) + Ps (8*16*72 u32) = 110592 B.
// ---------------------------------------------------------------------------
__global__ __launch_bounds__(256) void flash_attn()
{
    extern __shared__ uint32_t shm[];
    uint32_t* KsB = shm;                    // 2 * 64*72
    uint32_t* VsB = shm + 2 * 64 * KPAD;    // 2 * 64*72
    uint32_t* Ps  = shm + 4 * 64 * KPAD;    // 8 * 16*72

    const int h = blockIdx.y;
    const int q0 = blockIdx.x * 128;
    const int tid = threadIdx.x, lane = tid & 31, w = tid >> 5;
    const int g = lane >> 2, tig = lane & 3;
    uint32_t* myP = Ps + w * 16 * KPAD;

    // ---- stage this warp's 16x64 Q strip (tf32 bits) -> fragments in regs ----
    const float* Qg = g_Q + (size_t)(h * SEQ + q0 + w * 16) * HD;
#pragma unroll
    for (int j = 0; j < 8; j++) {
        int idx = lane + j * 32;                 // 256 float4 chunks
        int r = idx >> 4, c4 = (idx & 15) << 2;
        *(uint4*)&myP[r * KPAD + c4] = *(const uint4*)&Qg[r * HD + c4];
    }
    __syncwarp();
    uint32_t qf[8][4];
#pragma unroll
    for (int kk = 0; kk < 8; kk++) {
        qf[kk][0] = myP[g       * KPAD + kk * 8 + tig];
        qf[kk][1] = myP[(g + 8) * KPAD + kk * 8 + tig];
        qf[kk][2] = myP[g       * KPAD + kk * 8 + tig + 4];
        qf[kk][3] = myP[(g + 8) * KPAD + kk * 8 + tig + 4];
    }

    float oacc[8][4];
#pragma unroll
    for (int n = 0; n < 8; n++)
#pragma unroll
        for (int i = 0; i < 4; i++) oacc[n][i] = 0.f;
    float m0 = -1e30f, m1 = -1e30f, l0 = 0.f, l1 = 0.f;

    const float* Kh = g_K + (size_t)h * SEQ * HD;
    const float* Vh = g_V + (size_t)h * SEQ * HD;

    // issue tile 0
    {
#pragma unroll
        for (int j = 0; j < 4; j++) {
            int idx = tid + j * 256;               // 1024 chunks over 64x64
            int r = idx >> 4, c4 = (idx & 15) << 2;
            cp16(&KsB[r * KPAD + c4], &Kh[r * HD + c4]);
            cp16(&VsB[r * KPAD + c4], &Vh[r * HD + c4]);
        }
        cp_commit();
    }

    const int NT = SEQ / 64;
    for (int t = 0; t < NT; t++) {
        cp_wait0();
        __syncthreads();           // tile t visible; prior compute done -> safe to refill other buf
        if (t + 1 < NT) {
            int buf = (t + 1) & 1;
            const float* Kt = Kh + (size_t)(t + 1) * 64 * HD;
            const float* Vt = Vh + (size_t)(t + 1) * 64 * HD;
#pragma unroll
            for (int j = 0; j < 4; j++) {
                int idx = tid + j * 256;
                int r = idx >> 4, c4 = (idx & 15) << 2;
                cp16(&KsB[buf * 64 * KPAD + r * KPAD + c4], &Kt[r * HD + c4]);
                cp16(&VsB[buf * 64 * KPAD + r * KPAD + c4], &Vt[r * HD + c4]);
            }
            cp_commit();
        }
        const uint32_t* Ks = KsB + (t & 1) * 64 * KPAD;
        const uint32_t* Vs = VsB + (t & 1) * 64 * KPAD;

        // ---- S = Q @ K^T : 8 n-tiles of m16n8, accumulate over 8 k-tiles ----
        float sacc[8][4];
#pragma unroll
        for (int n = 0; n < 8; n++)
#pragma unroll
            for (int i = 0; i < 4; i++) sacc[n][i] = 0.f;
#pragma unroll
        for (int kk = 0; kk < 8; kk++) {
#pragma unroll
            for (int n = 0; n < 8; n++) {
                uint32_t bb[2];
                bb[0] = Ks[(n * 8 + g) * KPAD + kk * 8 + tig];
                bb[1] = Ks[(n * 8 + g) * KPAD + kk * 8 + tig + 4];
                mma8(sacc[n], qf[kk], bb);
            }
        }

        // ---- online softmax in registers (rows g and g+8 of this warp strip) ----
        float mx0 = -1e30f, mx1 = -1e30f;
#pragma unroll
        for (int n = 0; n < 8; n++) {
            mx0 = fmaxf(mx0, fmaxf(sacc[n][0], sacc[n][1]));
            mx1 = fmaxf(mx1, fmaxf(sacc[n][2], sacc[n][3]));
        }
        mx0 = fmaxf(mx0, __shfl_xor_sync(0xffffffffu, mx0, 1));
        mx0 = fmaxf(mx0, __shfl_xor_sync(0xffffffffu, mx0, 2));
        mx1 = fmaxf(mx1, __shfl_xor_sync(0xffffffffu, mx1, 1));
        mx1 = fmaxf(mx1, __shfl_xor_sync(0xffffffffu, mx1, 2));
        float nm0 = fmaxf(m0, mx0), nm1 = fmaxf(m1, mx1);
        float a0 = __expf(m0 - nm0), a1 = __expf(m1 - nm1);
        float s0 = 0.f, s1 = 0.f;
#pragma unroll
        for (int n = 0; n < 8; n++) {
            float p00 = __expf(sacc[n][0] - nm0);
            float p01 = __expf(sacc[n][1] - nm0);
            float p10 = __expf(sacc[n][2] - nm1);
            float p11 = __expf(sacc[n][3] - nm1);
            s0 += p00 + p01; s1 += p10 + p11;
            uint2 lo = make_uint2(f2tf(p00), f2tf(p01));
            uint2 hi = make_uint2(f2tf(p10), f2tf(p11));
            *(uint2*)&myP[g       * KPAD + n * 8 + 2 * tig] = lo;
            *(uint2*)&myP[(g + 8) * KPAD + n * 8 + 2 * tig] = hi;
        }
        s0 += __shfl_xor_sync(0xffffffffu, s0, 1);
        s0 += __shfl_xor_sync(0xffffffffu, s0, 2);
        s1 += __shfl_xor_sync(0xffffffffu, s1, 1);
        s1 += __shfl_xor_sync(0xffffffffu, s1, 2);
        m0 = nm0; m1 = nm1;
        l0 = l0 * a0 + s0; l1 = l1 * a1 + s1;
#pragma unroll
        for (int n = 0; n < 8; n++) {
            oacc[n][0] *= a0; oacc[n][1] *= a0;
            oacc[n][2] *= a1; oacc[n][3] *= a1;
        }
        __syncwarp();

        // ---- O += P @ V ----
#pragma unroll
        for (int kk = 0; kk < 8; kk++) {
            uint32_t pa[4];
            pa[0] = myP[g       * KPAD + kk * 8 + tig];
            pa[1] = myP[(g + 8) * KPAD + kk * 8 + tig];
            pa[2] = myP[g       * KPAD + kk * 8 + tig + 4];
            pa[3] = myP[(g + 8) * KPAD + kk * 8 + tig + 4];
#pragma unroll
            for (int n = 0; n < 8; n++) {
                uint32_t vb[2];
                vb[0] = Vs[(kk * 8 + tig)     * KPAD + n * 8 + g];
                vb[1] = Vs[(kk * 8 + tig + 4) * KPAD + n * 8 + g];
                mma8(oacc[n], pa, vb);
            }
        }
    }

    // ---- finalize: O/l -> g_O[s][h*64+d] ----
    float inv0 = 1.0f / l0, inv1 = 1.0f / l1;
    int r0 = q0 + w * 16 + g, r1 = r0 + 8;
#pragma unroll
    for (int n = 0; n < 8; n++) {
        int col = h * HD + n * 8 + 2 * tig;
        *(float2*)&g_O[r0 * EMB + col] = make_float2(oacc[n][0] * inv0, oacc[n][1] * inv0);
        *(float2*)&g_O[r1 * EMB + col] = make_float2(oacc[n][2] * inv1, oacc[n][3] * inv1);
    }
}

// ---------------------------------------------------------------------------

extern "C" void kernel_launch(void* const* d_in, const int* in_sizes, int n_in,
                              void* d_out, int out_size)
{
    const float* x  = (const float*)d_in[0];
    const float* Wq = (const float*)d_in[1];
    const float* bq = (const float*)d_in[2];
    const float* Wk = (const float*)d_in[3];
    const float* bk = (const float*)d_in[4];
    const float* Wv = (const float*)d_in[5];
    const float* bv = (const float*)d_in[6];
    const float* Wo = (const float*)d_in[7];
    const float* bo = (const float*)d_in[8];
    float* out = (float*)d_out;

    cudaFuncSetAttribute(flash_attn, cudaFuncAttributeMaxDynamicSharedMemorySize, 110592);

    qkv_gemm<<<dim3(EMB / 128, SEQ / 128, 3), 256>>>(x, Wq, Wk, Wv, bq, bk, bv);
    flash_attn<<<dim3(SEQ / 128, NH), 256, 110592>>>();
    out_gemm<<<dim3(EMB / 128, SEQ / 128), 256>>>(Wo, bo, out);
}